// round 10
// baseline (speedup 1.0000x reference)
#include <cuda_runtime.h>
#include <cuda_fp16.h>

// LNCC, volumes (B=2, C=1, 192,192,192) fp32, kernel 5, zero padding.
// Normalizer is always 1/125 (separable 1/5 per axis, zeros outside).
//
// Two streaming kernels, TWO launches total (init/finalize folded into k_x):
//  K_zy: z-filter (in-thread, contiguous float4 windows) + y-filter (5-deep
//        per-thread smem ring, fp16 exact-cancel) -> 5-channel fp16 tensor.
//  K_x : streams x with the same ring trick, computes NCC per voxel, reduces
//        to scalar; last block finalizes and self-resets the accumulator.

#define NN    192
#define NZ4   48                  // 192/4 z-groups per line
#define V     14155776            // 2*192^3
#define CHUNK 48                  // streamed-axis chunk per block
#define NCHK  4                   // 192/48 chunks
#define TPB   128
#define COLS  18432               // 2*192*48 columns
#define BPC   (COLS / TPB)        // 144 blocks per chunk
#define NBLK  (NCHK * BPC)        // 576

__device__ __align__(16) __half g_mid[5 * V];   // [c][b][x][y][z], c-stride V
__device__ double   g_acc;        // zeroed at load; self-resets each run
__device__ unsigned g_cnt;

// 5-tap sliding window sums over p0..p7 -> 4 outputs.
__device__ __forceinline__ float4 win5(float p0, float p1, float p2, float p3,
                                       float p4, float p5, float p6, float p7) {
    float s0 = ((p0 + p1) + (p2 + p3)) + p4;
    float s1 = s0 - p0 + p5;
    float s2 = s1 - p1 + p6;
    float s3 = s2 - p2 + p7;
    return make_float4(s0, s1, s2, s3);
}

__device__ __forceinline__ uint2 packh4(float4 s) {
    union { uint2 u; __half2 h[2]; } pk;
    pk.h[0] = __floats2half2_rn(s.x, s.y);
    pk.h[1] = __floats2half2_rn(s.z, s.w);
    return pk.u;
}

__device__ __forceinline__ float4 unpackh4(uint2 u) {
    union { uint2 u; __half2 h[2]; } pk;
    pk.u = u;
    float2 a = __half22float2(pk.h[0]);
    float2 b = __half22float2(pk.h[1]);
    return make_float4(a.x, a.y, b.x, b.y);
}

// ---------------------------------------------------------------------------
// K_zy: thread owns column (b, x, z4) and streams y over one 48-chunk.
// ---------------------------------------------------------------------------
__global__ void __launch_bounds__(TPB) k_zy(const float* __restrict__ I,
                                            const float* __restrict__ J) {
    __shared__ uint2 ring[5][5][TPB];           // [slot][ch][tid] = 25.6 KB

    int tid = threadIdx.x;
    int yc  = blockIdx.x / BPC;
    int cid = (blockIdx.x % BPC) * TPB + tid;   // column id
    int z4  = cid % NZ4;
    int xr  = cid / NZ4;
    int x   = xr % NN;
    int b   = xr / NN;
    int colbase = (b * NN + x) * NN;            // (colbase + y)*NN + z
    int y0 = yc * CHUNK;

    float acc[5][4];
#pragma unroll
    for (int c = 0; c < 5; c++)
#pragma unroll
        for (int j = 0; j < 4; j++) acc[c][j] = 0.f;

    const float4 zero4 = make_float4(0.f, 0.f, 0.f, 0.f);

#pragma unroll 2
    for (int t = 0; t < CHUNK + 4; t++) {
        int yy = y0 - 2 + t;
        float4 s[5];
        if ((unsigned)yy < (unsigned)NN) {
            int base = (colbase + yy) * NN + z4 * 4;
            const float4* pi = reinterpret_cast<const float4*>(I + base);
            const float4* pj = reinterpret_cast<const float4*>(J + base);
            float4 im = (z4 > 0)       ? pi[-1] : zero4;
            float4 ib = pi[0];
            float4 ip = (z4 < NZ4 - 1) ? pi[1]  : zero4;
            float4 jm = (z4 > 0)       ? pj[-1] : zero4;
            float4 jb = pj[0];
            float4 jp = (z4 < NZ4 - 1) ? pj[1]  : zero4;
            float i0 = im.z, i1 = im.w, i2 = ib.x, i3 = ib.y,
                  i4 = ib.z, i5 = ib.w, i6 = ip.x, i7 = ip.y;
            float j0 = jm.z, j1 = jm.w, j2 = jb.x, j3 = jb.y,
                  j4 = jb.z, j5 = jb.w, j6 = jp.x, j7 = jp.y;
            s[0] = win5(i0, i1, i2, i3, i4, i5, i6, i7);
            s[1] = win5(j0, j1, j2, j3, j4, j5, j6, j7);
            s[2] = win5(i0*i0, i1*i1, i2*i2, i3*i3, i4*i4, i5*i5, i6*i6, i7*i7);
            s[3] = win5(j0*j0, j1*j1, j2*j2, j3*j3, j4*j4, j5*j5, j6*j6, j7*j7);
            s[4] = win5(i0*j0, i1*j1, i2*j2, i3*j3, i4*j4, i5*j5, i6*j6, i7*j7);
        } else {
#pragma unroll
            for (int c = 0; c < 5; c++) s[c] = zero4;
        }

        int slot = t % 5;
        if (t >= 5) {
#pragma unroll
            for (int c = 0; c < 5; c++) {
                float4 o = unpackh4(ring[slot][c][tid]);   // value from t-5
                acc[c][0] -= o.x; acc[c][1] -= o.y;
                acc[c][2] -= o.z; acc[c][3] -= o.w;
            }
        }
#pragma unroll
        for (int c = 0; c < 5; c++) {
            uint2 p = packh4(s[c]);                        // round first
            ring[slot][c][tid] = p;
            float4 r = unpackh4(p);                        // exact-cancel value
            acc[c][0] += r.x; acc[c][1] += r.y;
            acc[c][2] += r.z; acc[c][3] += r.w;
        }

        if (t >= 4) {
            int yo = y0 + t - 4;
            int off = (colbase + yo) * NN + z4 * 4;
#pragma unroll
            for (int c = 0; c < 5; c++) {
                float4 a = make_float4(acc[c][0], acc[c][1], acc[c][2], acc[c][3]);
                *reinterpret_cast<uint2*>(g_mid + c * V + off) = packh4(a);
            }
        }
    }
}

// ---------------------------------------------------------------------------
// K_x: thread owns column (b, y, z4), streams x over one 48-chunk, computes
// NCC, reduces; last finished block writes the output and resets state.
// ---------------------------------------------------------------------------
__global__ void __launch_bounds__(TPB) k_x(float* __restrict__ out) {
    __shared__ uint2 ring[5][5][TPB];
    __shared__ float ws[TPB / 32];

    int tid = threadIdx.x;
    int xc  = blockIdx.x / BPC;
    int cid = (blockIdx.x % BPC) * TPB + tid;
    int z4  = cid % NZ4;
    int yr  = cid / NZ4;
    int y   = yr % NN;
    int b   = yr / NN;
    int x0  = xc * CHUNK;

    float acc[5][4];
#pragma unroll
    for (int c = 0; c < 5; c++)
#pragma unroll
        for (int j = 0; j < 4; j++) acc[c][j] = 0.f;

    float local = 0.f;
    const float inv = 1.0f / 125.0f;

#pragma unroll 2
    for (int t = 0; t < CHUNK + 4; t++) {
        int xx = x0 - 2 + t;
        uint2 v[5];
        if ((unsigned)xx < (unsigned)NN) {
            int off = ((b * NN + xx) * NN + y) * NN + z4 * 4;
#pragma unroll
            for (int c = 0; c < 5; c++)
                v[c] = *reinterpret_cast<const uint2*>(g_mid + c * V + off);
        } else {
#pragma unroll
            for (int c = 0; c < 5; c++) v[c] = make_uint2(0u, 0u);
        }

        int slot = t % 5;
        if (t >= 5) {
#pragma unroll
            for (int c = 0; c < 5; c++) {
                float4 o = unpackh4(ring[slot][c][tid]);
                acc[c][0] -= o.x; acc[c][1] -= o.y;
                acc[c][2] -= o.z; acc[c][3] -= o.w;
            }
        }
#pragma unroll
        for (int c = 0; c < 5; c++) {
            ring[slot][c][tid] = v[c];
            float4 r = unpackh4(v[c]);
            acc[c][0] += r.x; acc[c][1] += r.y;
            acc[c][2] += r.z; acc[c][3] += r.w;
        }

        if (t >= 4) {
#pragma unroll
            for (int j = 0; j < 4; j++) {
                float uI  = acc[0][j] * inv;
                float uJ  = acc[1][j] * inv;
                float mI2 = acc[2][j] * inv;
                float mJ2 = acc[3][j] * inv;
                float mIJ = acc[4][j] * inv;
                float cross = mIJ - uI * uJ;
                float vI = mI2 - uI * uI;
                float vJ = mJ2 - uJ * uJ;
                local += __fdividef(cross * cross, vI * vJ + 1e-5f);
            }
        }
    }

    // block reduction (4 warps) -> double atomic -> last-block finalize
#pragma unroll
    for (int o = 16; o; o >>= 1)
        local += __shfl_down_sync(0xffffffffu, local, o);
    int lane = tid & 31, wid = tid >> 5;
    if (lane == 0) ws[wid] = local;
    __syncthreads();
    if (tid == 0) {
        float vv = ws[0] + ws[1] + ws[2] + ws[3];
        atomicAdd(&g_acc, (double)vv);
        __threadfence();
        unsigned done = atomicAdd(&g_cnt, 1u);
        if (done == (unsigned)(NBLK - 1)) {
            double total = atomicAdd(&g_acc, 0.0);   // coherent read
            out[0] = (float)(-total / (double)V);
            g_acc = 0.0;                              // reset for next replay
            g_cnt = 0u;
            __threadfence();
        }
    }
}

extern "C" void kernel_launch(void* const* d_in, const int* in_sizes, int n_in,
                              void* d_out, int out_size) {
    const float* pred = (const float*)d_in[0];
    const float* targ = (const float*)d_in[1];
    (void)in_sizes; (void)n_in; (void)out_size;

    k_zy<<<NBLK, TPB>>>(pred, targ);   // 576 blocks
    k_x<<<NBLK, TPB>>>((float*)d_out); // 576 blocks
}

// round 12
// speedup vs baseline: 1.5216x; 1.5216x over previous
#include <cuda_runtime.h>
#include <cuda_fp16.h>

// LNCC, volumes (B=2, C=1, 192,192,192) fp32, kernel 5, zero padding.
// Normalizer is always 1/125 (separable 1/5 per axis, zeros outside).
//
// Two streaming kernels, TWO launches total (init/finalize folded into k_x).
// CHUNK=24 (1152 blocks, ~7.8 CTAs/SM) — measured-good occupancy point (R2);
// CHUNK=48 regressed badly (occ 23%, issue-bound latency exposure, R10).

#define NN    192
#define NZ4   48                  // 192/4 z-groups per line
#define V     14155776            // 2*192^3
#define CHUNK 24                  // streamed-axis chunk per block
#define NCHK  8                   // 192/24 chunks
#define TPB   128
#define COLS  18432               // 2*192*48 columns
#define BPC   (COLS / TPB)        // 144 blocks per chunk
#define NBLK  (NCHK * BPC)        // 1152

__device__ __align__(16) __half g_mid[5 * V];   // [c][b][x][y][z], c-stride V
__device__ double   g_acc;        // zeroed at load; self-resets each run
__device__ unsigned g_cnt;

// 5-tap sliding window sums over p0..p7 -> 4 outputs.
__device__ __forceinline__ float4 win5(float p0, float p1, float p2, float p3,
                                       float p4, float p5, float p6, float p7) {
    float s0 = ((p0 + p1) + (p2 + p3)) + p4;
    float s1 = s0 - p0 + p5;
    float s2 = s1 - p1 + p6;
    float s3 = s2 - p2 + p7;
    return make_float4(s0, s1, s2, s3);
}

__device__ __forceinline__ uint2 packh4(float4 s) {
    union { uint2 u; __half2 h[2]; } pk;
    pk.h[0] = __floats2half2_rn(s.x, s.y);
    pk.h[1] = __floats2half2_rn(s.z, s.w);
    return pk.u;
}

__device__ __forceinline__ float4 unpackh4(uint2 u) {
    union { uint2 u; __half2 h[2]; } pk;
    pk.u = u;
    float2 a = __half22float2(pk.h[0]);
    float2 b = __half22float2(pk.h[1]);
    return make_float4(a.x, a.y, b.x, b.y);
}

// ---------------------------------------------------------------------------
// K_zy: thread owns column (b, x, z4) and streams y over one 24-chunk.
// z-filter in registers from raw fp32; y-filter via 5-deep per-thread smem
// ring of fp16-rounded slices (exact cancel); writes zy-filtered fp16.
// ---------------------------------------------------------------------------
__global__ void __launch_bounds__(TPB) k_zy(const float* __restrict__ I,
                                            const float* __restrict__ J) {
    __shared__ uint2 ring[5][5][TPB];           // [slot][ch][tid] = 25.6 KB

    int tid = threadIdx.x;
    int yc  = blockIdx.x / BPC;
    int cid = (blockIdx.x % BPC) * TPB + tid;   // column id
    int z4  = cid % NZ4;
    int xr  = cid / NZ4;
    int x   = xr % NN;
    int b   = xr / NN;
    int colbase = (b * NN + x) * NN;            // (colbase + y)*NN + z
    int y0 = yc * CHUNK;

    float acc[5][4];
#pragma unroll
    for (int c = 0; c < 5; c++)
#pragma unroll
        for (int j = 0; j < 4; j++) acc[c][j] = 0.f;

    const float4 zero4 = make_float4(0.f, 0.f, 0.f, 0.f);

    for (int t = 0; t < CHUNK + 4; t++) {
        int yy = y0 - 2 + t;
        float4 s[5];
        if ((unsigned)yy < (unsigned)NN) {
            int base = (colbase + yy) * NN + z4 * 4;
            const float4* pi = reinterpret_cast<const float4*>(I + base);
            const float4* pj = reinterpret_cast<const float4*>(J + base);
            float4 im = (z4 > 0)       ? pi[-1] : zero4;
            float4 ib = pi[0];
            float4 ip = (z4 < NZ4 - 1) ? pi[1]  : zero4;
            float4 jm = (z4 > 0)       ? pj[-1] : zero4;
            float4 jb = pj[0];
            float4 jp = (z4 < NZ4 - 1) ? pj[1]  : zero4;
            float i0 = im.z, i1 = im.w, i2 = ib.x, i3 = ib.y,
                  i4 = ib.z, i5 = ib.w, i6 = ip.x, i7 = ip.y;
            float j0 = jm.z, j1 = jm.w, j2 = jb.x, j3 = jb.y,
                  j4 = jb.z, j5 = jb.w, j6 = jp.x, j7 = jp.y;
            s[0] = win5(i0, i1, i2, i3, i4, i5, i6, i7);
            s[1] = win5(j0, j1, j2, j3, j4, j5, j6, j7);
            s[2] = win5(i0*i0, i1*i1, i2*i2, i3*i3, i4*i4, i5*i5, i6*i6, i7*i7);
            s[3] = win5(j0*j0, j1*j1, j2*j2, j3*j3, j4*j4, j5*j5, j6*j6, j7*j7);
            s[4] = win5(i0*j0, i1*j1, i2*j2, i3*j3, i4*j4, i5*j5, i6*j6, i7*j7);
        } else {
#pragma unroll
            for (int c = 0; c < 5; c++) s[c] = zero4;
        }

        int slot = t % 5;
        if (t >= 5) {
#pragma unroll
            for (int c = 0; c < 5; c++) {
                float4 o = unpackh4(ring[slot][c][tid]);   // value from t-5
                acc[c][0] -= o.x; acc[c][1] -= o.y;
                acc[c][2] -= o.z; acc[c][3] -= o.w;
            }
        }
#pragma unroll
        for (int c = 0; c < 5; c++) {
            uint2 p = packh4(s[c]);                        // round first
            ring[slot][c][tid] = p;
            float4 r = unpackh4(p);                        // exact-cancel value
            acc[c][0] += r.x; acc[c][1] += r.y;
            acc[c][2] += r.z; acc[c][3] += r.w;
        }

        if (t >= 4) {
            int yo = y0 + t - 4;
            int off = (colbase + yo) * NN + z4 * 4;
#pragma unroll
            for (int c = 0; c < 5; c++) {
                float4 a = make_float4(acc[c][0], acc[c][1], acc[c][2], acc[c][3]);
                *reinterpret_cast<uint2*>(g_mid + c * V + off) = packh4(a);
            }
        }
    }
}

// ---------------------------------------------------------------------------
// K_x: thread owns column (b, y, z4), streams x over one 24-chunk, computes
// NCC, reduces; last finished block writes the output and resets state.
// ---------------------------------------------------------------------------
__global__ void __launch_bounds__(TPB) k_x(float* __restrict__ out) {
    __shared__ uint2 ring[5][5][TPB];
    __shared__ float ws[TPB / 32];

    int tid = threadIdx.x;
    int xc  = blockIdx.x / BPC;
    int cid = (blockIdx.x % BPC) * TPB + tid;
    int z4  = cid % NZ4;
    int yr  = cid / NZ4;
    int y   = yr % NN;
    int b   = yr / NN;
    int x0  = xc * CHUNK;

    float acc[5][4];
#pragma unroll
    for (int c = 0; c < 5; c++)
#pragma unroll
        for (int j = 0; j < 4; j++) acc[c][j] = 0.f;

    float local = 0.f;
    const float inv = 1.0f / 125.0f;

    for (int t = 0; t < CHUNK + 4; t++) {
        int xx = x0 - 2 + t;
        uint2 v[5];
        if ((unsigned)xx < (unsigned)NN) {
            int off = ((b * NN + xx) * NN + y) * NN + z4 * 4;
#pragma unroll
            for (int c = 0; c < 5; c++)
                v[c] = *reinterpret_cast<const uint2*>(g_mid + c * V + off);
        } else {
#pragma unroll
            for (int c = 0; c < 5; c++) v[c] = make_uint2(0u, 0u);
        }

        int slot = t % 5;
        if (t >= 5) {
#pragma unroll
            for (int c = 0; c < 5; c++) {
                float4 o = unpackh4(ring[slot][c][tid]);
                acc[c][0] -= o.x; acc[c][1] -= o.y;
                acc[c][2] -= o.z; acc[c][3] -= o.w;
            }
        }
#pragma unroll
        for (int c = 0; c < 5; c++) {
            ring[slot][c][tid] = v[c];
            float4 r = unpackh4(v[c]);
            acc[c][0] += r.x; acc[c][1] += r.y;
            acc[c][2] += r.z; acc[c][3] += r.w;
        }

        if (t >= 4) {
#pragma unroll
            for (int j = 0; j < 4; j++) {
                float uI  = acc[0][j] * inv;
                float uJ  = acc[1][j] * inv;
                float mI2 = acc[2][j] * inv;
                float mJ2 = acc[3][j] * inv;
                float mIJ = acc[4][j] * inv;
                float cross = mIJ - uI * uJ;
                float vI = mI2 - uI * uI;
                float vJ = mJ2 - uJ * uJ;
                local += __fdividef(cross * cross, vI * vJ + 1e-5f);
            }
        }
    }

    // block reduction (4 warps) -> double atomic -> last-block finalize
#pragma unroll
    for (int o = 16; o; o >>= 1)
        local += __shfl_down_sync(0xffffffffu, local, o);
    int lane = tid & 31, wid = tid >> 5;
    if (lane == 0) ws[wid] = local;
    __syncthreads();
    if (tid == 0) {
        float vv = ws[0] + ws[1] + ws[2] + ws[3];
        atomicAdd(&g_acc, (double)vv);
        __threadfence();
        unsigned done = atomicAdd(&g_cnt, 1u);
        if (done == (unsigned)(NBLK - 1)) {
            double total = atomicAdd(&g_acc, 0.0);   // coherent read
            out[0] = (float)(-total / (double)V);
            g_acc = 0.0;                              // reset for next replay
            g_cnt = 0u;
            __threadfence();
        }
    }
}

extern "C" void kernel_launch(void* const* d_in, const int* in_sizes, int n_in,
                              void* d_out, int out_size) {
    const float* pred = (const float*)d_in[0];
    const float* targ = (const float*)d_in[1];
    (void)in_sizes; (void)n_in; (void)out_size;

    k_zy<<<NBLK, TPB>>>(pred, targ);   // 1152 blocks
    k_x<<<NBLK, TPB>>>((float*)d_out); // 1152 blocks
}